// round 8
// baseline (speedup 1.0000x reference)
#include <cuda_runtime.h>
#include <math.h>

#define BATCH 256
#define NPOS 4
#define NNEG 1024
#define DIM 512
#define TEMP_INV 10.0f        // 1 / 0.1
#define POSW 0.3f
#define GRID 1368             // 152 SMs * 9 CTAs -> one balanced resident wave
#define TOTAL_ROWS (BATCH * NNEG)

// Scratch (device globals, zero-initialized at load; reset by last CTA each run)
__device__ float g_pz[BATCH];             // sum over negs of exp(10*sim)
__device__ int   g_pc[BATCH * NPOS];      // #neg sim > pos sim[p]
__device__ float g_possim[BATCH * NPOS];  // raw pos cosine sims
__device__ int   g_arrive = 0;            // arrival counter

__device__ __forceinline__ float dot16t(const float4& x0, const float4& x1,
                                        const float4& x2, const float4& x3,
                                        const float4& y0, const float4& y1,
                                        const float4& y2, const float4& y3) {
    float p0 = x0.x * y0.x; p0 = fmaf(x0.y, y0.y, p0); p0 = fmaf(x0.z, y0.z, p0); p0 = fmaf(x0.w, y0.w, p0);
    float p1 = x1.x * y1.x; p1 = fmaf(x1.y, y1.y, p1); p1 = fmaf(x1.z, y1.z, p1); p1 = fmaf(x1.w, y1.w, p1);
    float p2 = x2.x * y2.x; p2 = fmaf(x2.y, y2.y, p2); p2 = fmaf(x2.z, y2.z, p2); p2 = fmaf(x2.w, y2.w, p2);
    float p3 = x3.x * y3.x; p3 = fmaf(x3.y, y3.y, p3); p3 = fmaf(x3.z, y3.z, p3); p3 = fmaf(x3.w, y3.w, p3);
    return (p0 + p1) + (p2 + p3);
}

__global__ __launch_bounds__(128, 9)
void rrl_persist(const float* __restrict__ anchor,
                 const float* __restrict__ positives,
                 const float* __restrict__ negatives,
                 float* __restrict__ out) {
    const int tid  = threadIdx.x;
    const int lane = tid & 31;
    const int warp = tid >> 5;
    const int cta  = blockIdx.x;

    // flat row range for this CTA (equal +-1)
    int cnt = TOTAL_ROWS / GRID;
    const int rem = TOTAL_ROWS - cnt * GRID;
    int start = cta * cnt + min(cta, rem);
    if (cta < rem) cnt++;
    const int end = start + cnt;

    __shared__ float s_psim[NPOS];
    __shared__ int   s_last;

    int row = start;
    while (row < end) {
        const int b    = row >> 10;               // row / NNEG
        const int bend = min(end, (b + 1) << 10);
        __syncthreads();                          // protect s_psim reuse

        // --- anchor slice (per-warp copy): lane covers float4 chunks lane + k*32 ---
        const float4* a4 = (const float4*)(anchor + (size_t)b * DIM);
        const float4 a0 = a4[lane], a1 = a4[lane + 32], a2 = a4[lane + 64], a3 = a4[lane + 96];
        float asq = dot16t(a0, a1, a2, a3, a0, a1, a2, a3);
        #pragma unroll
        for (int o = 16; o; o >>= 1) asq += __shfl_xor_sync(0xffffffffu, asq, o);
        const float inva = rsqrtf(asq);           // 1 / ||a||

        // --- positive sims: warp w computes positive w, share via smem ---
        {
            const float4* p4 = (const float4*)(positives + ((size_t)b * NPOS + warp) * DIM);
            const float4 p0 = p4[lane], p1 = p4[lane + 32], p2 = p4[lane + 64], p3 = p4[lane + 96];
            float pd = dot16t(p0, p1, p2, p3, a0, a1, a2, a3);
            float pq = dot16t(p0, p1, p2, p3, p0, p1, p2, p3);
            #pragma unroll
            for (int o = 16; o; o >>= 1) {
                pd += __shfl_xor_sync(0xffffffffu, pd, o);
                pq += __shfl_xor_sync(0xffffffffu, pq, o);
            }
            if (lane == 0) {
                const float sim = pd * rsqrtf(pq) * inva;
                s_psim[warp] = sim;
                g_possim[b * NPOS + warp] = sim;  // duplicate identical writes: benign
            }
        }
        __syncthreads();
        const float p0s = s_psim[0], p1s = s_psim[1], p2s = s_psim[2], p3s = s_psim[3];

        // --- stream rows [row, bend): warp-per-row, 2x pairing for MLP ---
        const float4* nbase = (const float4*)negatives;
        float z = 0.0f;
        int c0 = 0, c1 = 0, c2 = 0, c3 = 0;

        int j = row + warp;
        for (; j + 4 < bend; j += 8) {
            const float4* na = nbase + (size_t)j * (DIM / 4);
            const float4* nb = nbase + (size_t)(j + 4) * (DIM / 4);
            const float4 u0 = __ldcs(na + lane), u1 = __ldcs(na + lane + 32),
                         u2 = __ldcs(na + lane + 64), u3 = __ldcs(na + lane + 96);
            const float4 v0 = __ldcs(nb + lane), v1 = __ldcs(nb + lane + 32),
                         v2 = __ldcs(nb + lane + 64), v3 = __ldcs(nb + lane + 96);

            float da = dot16t(u0, u1, u2, u3, a0, a1, a2, a3);
            float sa = dot16t(u0, u1, u2, u3, u0, u1, u2, u3);
            float db = dot16t(v0, v1, v2, v3, a0, a1, a2, a3);
            float sb = dot16t(v0, v1, v2, v3, v0, v1, v2, v3);
            #pragma unroll
            for (int o = 16; o; o >>= 1) {
                da += __shfl_xor_sync(0xffffffffu, da, o);
                sa += __shfl_xor_sync(0xffffffffu, sa, o);
                db += __shfl_xor_sync(0xffffffffu, db, o);
                sb += __shfl_xor_sync(0xffffffffu, sb, o);
            }
            const float sima = da * rsqrtf(sa) * inva;
            const float simb = db * rsqrtf(sb) * inva;
            z += __expf(sima * TEMP_INV) + __expf(simb * TEMP_INV);
            c0 += (sima > p0s) + (simb > p0s);
            c1 += (sima > p1s) + (simb > p1s);
            c2 += (sima > p2s) + (simb > p2s);
            c3 += (sima > p3s) + (simb > p3s);
        }
        if (j < bend) {
            const float4* na = nbase + (size_t)j * (DIM / 4);
            const float4 u0 = __ldcs(na + lane), u1 = __ldcs(na + lane + 32),
                         u2 = __ldcs(na + lane + 64), u3 = __ldcs(na + lane + 96);
            float da = dot16t(u0, u1, u2, u3, a0, a1, a2, a3);
            float sa = dot16t(u0, u1, u2, u3, u0, u1, u2, u3);
            #pragma unroll
            for (int o = 16; o; o >>= 1) {
                da += __shfl_xor_sync(0xffffffffu, da, o);
                sa += __shfl_xor_sync(0xffffffffu, sa, o);
            }
            const float sima = da * rsqrtf(sa) * inva;
            z += __expf(sima * TEMP_INV);
            c0 += (sima > p0s); c1 += (sima > p1s); c2 += (sima > p2s); c3 += (sima > p3s);
        }

        // lanes hold identical reduced state; lane 0 merges to global
        if (lane == 0) {
            atomicAdd(&g_pz[b], z);
            atomicAdd(&g_pc[b * NPOS + 0], c0);
            atomicAdd(&g_pc[b * NPOS + 1], c1);
            atomicAdd(&g_pc[b * NPOS + 2], c2);
            atomicAdd(&g_pc[b * NPOS + 3], c3);
        }
        row = bend;
    }

    __threadfence();
    __syncthreads();
    if (tid == 0) s_last = (atomicAdd(&g_arrive, 1) == GRID - 1);
    __syncthreads();
    if (!s_last) return;

    // ============ last CTA: final math. 128 threads, 2 batch rows each ============
    {
        __shared__ float s_err[128];
        __shared__ float s_pos[128];

        float err = 0.0f, psum = 0.0f;
        #pragma unroll
        for (int h = 0; h < 2; h++) {
            const int r = tid + h * 128;
            float ps[NPOS], ex[NPOS];
            float Z = g_pz[r];
            #pragma unroll
            for (int p = 0; p < NPOS; p++) {
                ps[p] = g_possim[r * NPOS + p];
                ex[p] = __expf(ps[p] * TEMP_INV);
                Z += ex[p];
            }
            #pragma unroll
            for (int p = 0; p < NPOS; p++) {
                int cntp = g_pc[r * NPOS + p];
                #pragma unroll
                for (int q = 0; q < NPOS; q++)
                    cntp += (ps[q] > ps[p]) || ((ps[q] == ps[p]) && (q < p));  // stable ties
                err += (ex[p] / Z) * (1.0f / (float)(cntp + 1));
                psum += ps[p];
            }
        }
        s_err[tid] = err;
        s_pos[tid] = psum;
        __syncthreads();
        for (int step = 64; step > 0; step >>= 1) {
            if (tid < step) {
                s_err[tid] += s_err[tid + step];
                s_pos[tid] += s_pos[tid + step];
            }
            __syncthreads();
        }

        // reset scratch for next graph replay (after all reads above)
        #pragma unroll
        for (int h = 0; h < 2; h++) {
            const int r = tid + h * 128;
            g_pz[r] = 0.0f;
            #pragma unroll
            for (int p = 0; p < NPOS; p++) g_pc[r * NPOS + p] = 0;
        }
        if (tid == 0) {
            out[0] = -(s_err[0] / (float)BATCH)
                     + POSW * (1.0f - s_pos[0] / (float)(BATCH * NPOS));
            g_arrive = 0;
        }
    }
}

extern "C" void kernel_launch(void* const* d_in, const int* in_sizes, int n_in,
                              void* d_out, int out_size) {
    const float* anchor    = (const float*)d_in[0];
    const float* positives = (const float*)d_in[1];
    const float* negatives = (const float*)d_in[2];
    float* out = (float*)d_out;

    rrl_persist<<<GRID, 128>>>(anchor, positives, negatives, out);
}

// round 10
// speedup vs baseline: 1.0523x; 1.0523x over previous
#include <cuda_runtime.h>
#include <math.h>

#define BATCH 256
#define NPOS 4
#define NNEG 1024
#define DIM 512
#define TEMP_INV 10.0f        // 1 / 0.1
#define POSW 0.3f
#define GRID 1216             // 152 SMs * 8 CTAs -> one balanced resident wave
#define TOTAL_ROWS (BATCH * NNEG)

// Scratch (device globals, zero-initialized at load; reset by last CTA each run)
__device__ float g_pz[BATCH];             // sum over negs of exp(10*sim)
__device__ int   g_pc[BATCH * NPOS];      // #neg sim > pos sim[p]
__device__ float g_possim[BATCH * NPOS];  // raw pos cosine sims
__device__ int   g_arrive = 0;            // arrival counter

__device__ __forceinline__ float dot16t(const float4& x0, const float4& x1,
                                        const float4& x2, const float4& x3,
                                        const float4& y0, const float4& y1,
                                        const float4& y2, const float4& y3) {
    float p0 = x0.x * y0.x; p0 = fmaf(x0.y, y0.y, p0); p0 = fmaf(x0.z, y0.z, p0); p0 = fmaf(x0.w, y0.w, p0);
    float p1 = x1.x * y1.x; p1 = fmaf(x1.y, y1.y, p1); p1 = fmaf(x1.z, y1.z, p1); p1 = fmaf(x1.w, y1.w, p1);
    float p2 = x2.x * y2.x; p2 = fmaf(x2.y, y2.y, p2); p2 = fmaf(x2.z, y2.z, p2); p2 = fmaf(x2.w, y2.w, p2);
    float p3 = x3.x * y3.x; p3 = fmaf(x3.y, y3.y, p3); p3 = fmaf(x3.z, y3.z, p3); p3 = fmaf(x3.w, y3.w, p3);
    return (p0 + p1) + (p2 + p3);
}

__global__ __launch_bounds__(128, 8)
void rrl_persist(const float* __restrict__ anchor,
                 const float* __restrict__ positives,
                 const float* __restrict__ negatives,
                 float* __restrict__ out) {
    const int tid  = threadIdx.x;
    const int lane = tid & 31;
    const int warp = tid >> 5;
    const int cta  = blockIdx.x;

    // flat row range for this CTA (equal +-1)
    int cnt = TOTAL_ROWS / GRID;
    const int rem = TOTAL_ROWS - cnt * GRID;
    int start = cta * cnt + min(cta, rem);
    if (cta < rem) cnt++;
    const int end = start + cnt;

    __shared__ float s_psim[NPOS];
    __shared__ int   s_last;

    int row = start;
    while (row < end) {
        const int b    = row >> 10;               // row / NNEG
        const int bend = min(end, (b + 1) << 10);
        __syncthreads();                          // protect s_psim reuse

        // --- anchor slice (per-warp copy): lane covers float4 chunks lane + k*32 ---
        const float4* a4 = (const float4*)(anchor + (size_t)b * DIM);
        const float4 a0 = a4[lane], a1 = a4[lane + 32], a2 = a4[lane + 64], a3 = a4[lane + 96];
        float asq = dot16t(a0, a1, a2, a3, a0, a1, a2, a3);
        #pragma unroll
        for (int o = 16; o; o >>= 1) asq += __shfl_xor_sync(0xffffffffu, asq, o);
        const float inva = rsqrtf(asq);           // 1 / ||a||

        // --- positive sims: warp w computes positive w, share via smem ---
        {
            const float4* p4 = (const float4*)(positives + ((size_t)b * NPOS + warp) * DIM);
            const float4 p0 = p4[lane], p1 = p4[lane + 32], p2 = p4[lane + 64], p3 = p4[lane + 96];
            float pd = dot16t(p0, p1, p2, p3, a0, a1, a2, a3);
            float pq = dot16t(p0, p1, p2, p3, p0, p1, p2, p3);
            #pragma unroll
            for (int o = 16; o; o >>= 1) {
                pd += __shfl_xor_sync(0xffffffffu, pd, o);
                pq += __shfl_xor_sync(0xffffffffu, pq, o);
            }
            if (lane == 0) {
                const float sim = pd * rsqrtf(pq) * inva;
                s_psim[warp] = sim;
                g_possim[b * NPOS + warp] = sim;  // duplicate identical writes: benign
            }
        }
        __syncthreads();
        const float p0s = s_psim[0], p1s = s_psim[1], p2s = s_psim[2], p3s = s_psim[3];

        // --- stream rows [row, bend): warp-per-row, 2x pairing for MLP ---
        const float4* nbase = (const float4*)negatives;
        float z = 0.0f;
        int c0 = 0, c1 = 0, c2 = 0, c3 = 0;

        int j = row + warp;
        for (; j + 4 < bend; j += 8) {
            const float4* na = nbase + (size_t)j * (DIM / 4);
            const float4* nb = nbase + (size_t)(j + 4) * (DIM / 4);
            const float4 u0 = __ldcs(na + lane), u1 = __ldcs(na + lane + 32),
                         u2 = __ldcs(na + lane + 64), u3 = __ldcs(na + lane + 96);
            const float4 v0 = __ldcs(nb + lane), v1 = __ldcs(nb + lane + 32),
                         v2 = __ldcs(nb + lane + 64), v3 = __ldcs(nb + lane + 96);

            float da = dot16t(u0, u1, u2, u3, a0, a1, a2, a3);
            float sa = dot16t(u0, u1, u2, u3, u0, u1, u2, u3);
            float db = dot16t(v0, v1, v2, v3, a0, a1, a2, a3);
            float sb = dot16t(v0, v1, v2, v3, v0, v1, v2, v3);
            #pragma unroll
            for (int o = 16; o; o >>= 1) {
                da += __shfl_xor_sync(0xffffffffu, da, o);
                sa += __shfl_xor_sync(0xffffffffu, sa, o);
                db += __shfl_xor_sync(0xffffffffu, db, o);
                sb += __shfl_xor_sync(0xffffffffu, sb, o);
            }
            const float sima = da * rsqrtf(sa) * inva;
            const float simb = db * rsqrtf(sb) * inva;
            z += __expf(sima * TEMP_INV) + __expf(simb * TEMP_INV);
            c0 += (sima > p0s) + (simb > p0s);
            c1 += (sima > p1s) + (simb > p1s);
            c2 += (sima > p2s) + (simb > p2s);
            c3 += (sima > p3s) + (simb > p3s);
        }
        if (j < bend) {
            const float4* na = nbase + (size_t)j * (DIM / 4);
            const float4 u0 = __ldcs(na + lane), u1 = __ldcs(na + lane + 32),
                         u2 = __ldcs(na + lane + 64), u3 = __ldcs(na + lane + 96);
            float da = dot16t(u0, u1, u2, u3, a0, a1, a2, a3);
            float sa = dot16t(u0, u1, u2, u3, u0, u1, u2, u3);
            #pragma unroll
            for (int o = 16; o; o >>= 1) {
                da += __shfl_xor_sync(0xffffffffu, da, o);
                sa += __shfl_xor_sync(0xffffffffu, sa, o);
            }
            const float sima = da * rsqrtf(sa) * inva;
            z += __expf(sima * TEMP_INV);
            c0 += (sima > p0s); c1 += (sima > p1s); c2 += (sima > p2s); c3 += (sima > p3s);
        }

        // lanes hold identical reduced state; lane 0 merges to global
        if (lane == 0) {
            atomicAdd(&g_pz[b], z);
            atomicAdd(&g_pc[b * NPOS + 0], c0);
            atomicAdd(&g_pc[b * NPOS + 1], c1);
            atomicAdd(&g_pc[b * NPOS + 2], c2);
            atomicAdd(&g_pc[b * NPOS + 3], c3);
        }
        row = bend;
    }

    __threadfence();
    __syncthreads();
    if (tid == 0) s_last = (atomicAdd(&g_arrive, 1) == GRID - 1);
    __syncthreads();
    if (!s_last) return;

    // ============ last CTA: final math. 128 threads, 2 batch rows each ============
    {
        __shared__ float s_err[128];
        __shared__ float s_pos[128];

        float err = 0.0f, psum = 0.0f;
        #pragma unroll
        for (int h = 0; h < 2; h++) {
            const int r = tid + h * 128;
            float ps[NPOS], ex[NPOS];
            float Z = g_pz[r];
            #pragma unroll
            for (int p = 0; p < NPOS; p++) {
                ps[p] = g_possim[r * NPOS + p];
                ex[p] = __expf(ps[p] * TEMP_INV);
                Z += ex[p];
            }
            #pragma unroll
            for (int p = 0; p < NPOS; p++) {
                int cntp = g_pc[r * NPOS + p];
                #pragma unroll
                for (int q = 0; q < NPOS; q++)
                    cntp += (ps[q] > ps[p]) || ((ps[q] == ps[p]) && (q < p));  // stable ties
                err += (ex[p] / Z) * (1.0f / (float)(cntp + 1));
                psum += ps[p];
            }
        }
        s_err[tid] = err;
        s_pos[tid] = psum;
        __syncthreads();
        for (int step = 64; step > 0; step >>= 1) {
            if (tid < step) {
                s_err[tid] += s_err[tid + step];
                s_pos[tid] += s_pos[tid + step];
            }
            __syncthreads();
        }

        // reset scratch for next graph replay (after all reads above)
        #pragma unroll
        for (int h = 0; h < 2; h++) {
            const int r = tid + h * 128;
            g_pz[r] = 0.0f;
            #pragma unroll
            for (int p = 0; p < NPOS; p++) g_pc[r * NPOS + p] = 0;
        }
        if (tid == 0) {
            out[0] = -(s_err[0] / (float)BATCH)
                     + POSW * (1.0f - s_pos[0] / (float)(BATCH * NPOS));
            g_arrive = 0;
        }
    }
}

extern "C" void kernel_launch(void* const* d_in, const int* in_sizes, int n_in,
                              void* d_out, int out_size) {
    const float* anchor    = (const float*)d_in[0];
    const float* positives = (const float*)d_in[1];
    const float* negatives = (const float*)d_in[2];
    float* out = (float*)d_out;

    rrl_persist<<<GRID, 128>>>(anchor, positives, negatives, out);
}